// round 9
// baseline (speedup 1.0000x reference)
#include <cuda_runtime.h>

// CenterLoss collapses algebraically: after masking, only the true-label
// column survives; the other C-1 zeros clamp to 1e-12 each.
//   loss = sum_n clamp(||x_n - c_{lab_n}||^2, 1e-12, 1e12) + N*(C-1)*1e-12
//
// R9: tail-cost attack. Evidence: R2's pure gather kernel ran ~3.5us; all
// fused variants run ~8.2us regardless of body shape -> the ~4.4us delta is
// the completion tail (1024 serialized same-line atomics each CTA waits on,
// + fence + dependent tail read). This round: 256 CTAs x 1024 threads (same
// 8192 warps / same per-warp load pattern), so only 256 atomics and a
// 256-element L2-hot tail. Fixed-order reductions -> deterministic.

#define N_ROWS 4096      // 16 * 256
#define FEAT_DIM 512
#define F4_PER_ROW (FEAT_DIM / 4)   // 128
#define NUM_CLASSES 10000
#define NUM_CTAS 256
#define ROWS_PER_CTA 16              // 32 warps, half-row per warp

__device__ float g_cta_partials[NUM_CTAS];
__device__ unsigned int g_done_count = 0;

__global__ __launch_bounds__(1024, 2) void center_loss_kernel(
    const float* __restrict__ x,
    const int* __restrict__ labels,
    const float* __restrict__ centers,
    float* __restrict__ out)
{
    const int t = threadIdx.x;
    const int warp = t >> 5;          // 0..31
    const int lane = t & 31;
    const int cta = blockIdx.x;
    const int lrow = warp >> 1;       // 0..15 local row
    const int half = warp & 1;        // half of the row

    const int row = cta * ROWS_PER_CTA + lrow;

    __shared__ float s_half[32];
    __shared__ bool s_is_last;

    // Label first (head of the dependent chain), per-warp, no barrier.
    int c = 0;
    if (lane == 0) c = labels[row];

    // x loads overlap the label latency.
    const float4* __restrict__ xr =
        reinterpret_cast<const float4*>(x) + (size_t)row * F4_PER_ROW + half * 64;
    float4 a0 = xr[lane];
    float4 a1 = xr[32 + lane];

    c = __shfl_sync(0xffffffffu, c, 0);
    c = min(max(c, 0), NUM_CLASSES - 1);

    const float4* __restrict__ cr =
        reinterpret_cast<const float4*>(centers) + (size_t)c * F4_PER_ROW + half * 64;
    float4 b0 = cr[lane];
    float4 b1 = cr[32 + lane];

    float d0 = a0.x - b0.x, d1 = a0.y - b0.y, d2 = a0.z - b0.z, d3 = a0.w - b0.w;
    float s = d0 * d0 + d1 * d1 + d2 * d2 + d3 * d3;
    d0 = a1.x - b1.x; d1 = a1.y - b1.y; d2 = a1.z - b1.z; d3 = a1.w - b1.w;
    s += d0 * d0 + d1 * d1 + d2 * d2 + d3 * d3;

    #pragma unroll
    for (int o = 16; o > 0; o >>= 1)
        s += __shfl_xor_sync(0xffffffffu, s, o);

    if (lane == 0) s_half[warp] = s;
    __syncthreads();

    if (t == 0) {
        float acc = 0.0f;
        #pragma unroll
        for (int r = 0; r < ROWS_PER_CTA; r++) {
            float rs = s_half[2 * r] + s_half[2 * r + 1];
            rs = fminf(fmaxf(rs, 1e-12f), 1e12f);   // per-row clamp
            acc += rs;
        }
        g_cta_partials[cta] = acc;
        __threadfence();
        unsigned int v = atomicAdd(&g_done_count, 1u);
        s_is_last = (v == (unsigned int)(NUM_CTAS - 1));
    }
    __syncthreads();

    if (s_is_last) {
        // 256 partials, L2-hot (just written): one float per thread t<256.
        float v = (t < NUM_CTAS) ? g_cta_partials[t] : 0.0f;

        #pragma unroll
        for (int o = 16; o > 0; o >>= 1)
            v += __shfl_xor_sync(0xffffffffu, v, o);

        __shared__ float fs[32];
        if (lane == 0) fs[warp] = v;
        __syncthreads();

        if (t == 0) {
            const float zero_clamp_sum =
                (float)((double)N_ROWS * (double)(NUM_CLASSES - 1) * 1e-12);
            float r = 0.0f;
            #pragma unroll
            for (int w = 0; w < 8; w++) r += fs[w];   // warps 8..31 held zeros
            out[0] = r + zero_clamp_sum;
            g_done_count = 0;   // reset for next graph replay
        }
    }
}

extern "C" void kernel_launch(void* const* d_in, const int* in_sizes, int n_in,
                              void* d_out, int out_size)
{
    const float* x       = (const float*)d_in[0];  // (16,256,512) f32
    const int*   labels  = (const int*)d_in[1];    // (16,256) int32
    const float* centers = (const float*)d_in[2];  // (10000,512) f32
    float*       out     = (float*)d_out;          // scalar

    (void)in_sizes; (void)n_in; (void)out_size;

    center_loss_kernel<<<NUM_CTAS, 1024>>>(x, labels, centers, out);
}